// round 13
// baseline (speedup 1.0000x reference)
#include <cuda_runtime.h>
#include <cuda_fp16.h>
#include <cstdint>
#include <cstddef>

// ---------------------------------------------------------------------------
// GPTQ 4-bit: one merged prep pass (X f32->f16 + W dequant) + pure streaming
// fp16 HMMA GEMM, sm_103 base arch.
//
// R13 vs R12: register double-buffering of MMA fragments across kk-steps —
// LDSM for step kk+1 issues under the HMMAs of step kk, hiding shared-mem
// latency that previously serialized the start of every chunk. cp.async for
// chunk c+2 is issued right after the first MMA batch.
//
//   x      : float32 [4096, 4096]
//   qweight: int32   [512, 11008]  nibble j (shift 4*j) -> k = kp*8 + j
//   qzeros : int32   [1, 1376]     nibble (n%8) -> zero for col n; +1 (GPTQ)
//   scales : float32 [1, 11008]
//   out    : float32 [4096, 11008]
//
// K-permutation: g_Xh and g_Wt store each 8-group of K in pair order
// (t, t+4), matching ((q >> 4t) & 0x000F000F) | 0x64006400. Contraction
// is permutation-invariant. Dequant exact: w = ((1024+q) - (1025+z)) * s.
// ---------------------------------------------------------------------------

static constexpr int M_DIM = 4096;
static constexpr int K_DIM = 4096;
static constexpr int N_DIM = 11008;

static constexpr int BM = 128;
static constexpr int BN = 128;
static constexpr int BK = 64;                    // halves (128 B)
static constexpr int CHUNKS = K_DIM / BK;        // 64
static constexpr int STAGES = 3;
static constexpr int NTHREADS = 128;             // 4 warps

static constexpr uint32_t A_SZ = BM * 128;       // 16 KB
static constexpr uint32_t B_SZ = BN * 128;       // 16 KB
static constexpr uint32_t SMEM_BYTES = STAGES * (A_SZ + B_SZ);  // 96 KB

__device__ __half g_Xh[(size_t)M_DIM * K_DIM];   // 32 MB
__device__ __half g_Wt[(size_t)N_DIM * K_DIM];   // 90 MB, W^T [N][K]

// ---------------- helpers ----------------
__device__ __forceinline__ uint32_t h2u(__half2 h) { return *reinterpret_cast<uint32_t*>(&h); }
__device__ __forceinline__ __half2  u2h(uint32_t u) { return *reinterpret_cast<__half2*>(&u); }
__device__ __forceinline__ float    rnd16(float x) { return __half2float(__float2half_rn(x)); }

__device__ __forceinline__ void cp16(uint32_t dst, const void* src) {
    asm volatile("cp.async.cg.shared.global [%0], [%1], 16;" :: "r"(dst), "l"(src));
}
__device__ __forceinline__ void ldsm4(uint32_t* r, uint32_t addr) {
    asm volatile("ldmatrix.sync.aligned.m8n8.x4.shared.b16 {%0,%1,%2,%3}, [%4];"
                 : "=r"(r[0]), "=r"(r[1]), "=r"(r[2]), "=r"(r[3]) : "r"(addr));
}
__device__ __forceinline__ void mma16816(float* c, const uint32_t* a,
                                         uint32_t b0, uint32_t b1) {
    asm volatile("mma.sync.aligned.m16n8k16.row.col.f32.f16.f16.f32 "
                 "{%0,%1,%2,%3}, {%4,%5,%6,%7}, {%8,%9}, {%0,%1,%2,%3};"
                 : "+f"(c[0]), "+f"(c[1]), "+f"(c[2]), "+f"(c[3])
                 : "r"(a[0]), "r"(a[1]), "r"(a[2]), "r"(a[3]), "r"(b0), "r"(b1));
}

// ---------------------------------------------------------------------------
// Merged prep: blocks [0, XBLK) convert X; blocks [XBLK, XBLK+WBLK) dequant W.
// ---------------------------------------------------------------------------
static constexpr int XGROUPS = M_DIM * (K_DIM / 8);            // 2M
static constexpr int XBLK    = XGROUPS / 256;                   // 8192
static constexpr long long WGROUPS = (long long)N_DIM * (K_DIM / 16);
static constexpr int WBLK    = (int)((WGROUPS + 255) / 256);    // 11008

__global__ void __launch_bounds__(256)
prep(const float* __restrict__ X,
     const int*   __restrict__ qweight,
     const int*   __restrict__ qzeros,
     const float* __restrict__ scales) {
    if (blockIdx.x < XBLK) {
        const size_t e = (size_t)blockIdx.x * 256 + threadIdx.x;
        const float4* s = reinterpret_cast<const float4*>(X) + e * 2;
        const float4 lo = s[0];
        const float4 hi = s[1];
        uint4 o;
        o.x = h2u(__floats2half2_rn(lo.x, hi.x));
        o.y = h2u(__floats2half2_rn(lo.y, hi.y));
        o.z = h2u(__floats2half2_rn(lo.z, hi.z));
        o.w = h2u(__floats2half2_rn(lo.w, hi.w));
        reinterpret_cast<uint4*>(g_Xh)[e] = o;
    } else {
        const size_t idx = (size_t)(blockIdx.x - XBLK) * 256 + threadIdx.x;
        if (idx >= (size_t)WGROUPS) return;
        const int n   = (int)(idx % N_DIM);
        const int kp2 = (int)(idx / N_DIM);      // 0..255
        const int kp  = kp2 * 2;

        const int zraw = (qzeros[n >> 3] >> ((n & 7) * 4)) & 0xF;
        const __half2 z2 = __half2half2(__float2half_rn((float)(1025 + zraw)));
        const __half2 s2 = __half2half2(__float2half_rn(scales[n]));

        __half* dst = g_Wt + (size_t)n * K_DIM + kp * 8;
#pragma unroll
        for (int w2 = 0; w2 < 2; ++w2) {
            const uint32_t w = (uint32_t)qweight[(size_t)(kp + w2) * N_DIM + n];
            uint4 o;
            uint32_t* u = reinterpret_cast<uint32_t*>(&o);
#pragma unroll
            for (int t = 0; t < 4; ++t) {
                const uint32_t hb = ((w >> (4 * t)) & 0x000F000Fu) | 0x64006400u;
                u[t] = h2u(__hmul2(__hsub2(u2h(hb), z2), s2));
            }
            *reinterpret_cast<uint4*>(dst + w2 * 8) = o;
        }
    }
}

// ---------------------------------------------------------------------------
// Streaming fp16 GEMM: CTA 128x128x64, 4 warps (2m x 2n of 64x64),
// cp.async 3 stages, 1 barrier/chunk, 2 CTAs/SM,
// register double-buffered fragments across kk-steps.
// ---------------------------------------------------------------------------
__global__ void __launch_bounds__(NTHREADS, 2)
gemm_mma(float* __restrict__ Y) {
    extern __shared__ char smem[];
    const uint32_t sb = (uint32_t)__cvta_generic_to_shared(smem);

    const int tid  = threadIdx.x;
    const int warp = tid >> 5;
    const int lane = tid & 31;
    const int wm   = warp >> 1;      // 0..1  (64-row slice)
    const int wn   = warp & 1;       // 0..1  (64-col slice)
    const int bm   = blockIdx.y * BM;
    const int bn   = blockIdx.x * BN;

    float acc[4][8][4];
#pragma unroll
    for (int i = 0; i < 4; ++i)
#pragma unroll
        for (int j = 0; j < 8; ++j)
#pragma unroll
            for (int t = 0; t < 4; ++t) acc[i][j][t] = 0.0f;

    // precomputed per-thread LDSM row/swizzle components (constant across kk)
    const int aRow[4] = { wm * 64 + 0 * 16 + (lane & 15),
                          wm * 64 + 1 * 16 + (lane & 15),
                          wm * 64 + 2 * 16 + (lane & 15),
                          wm * 64 + 3 * 16 + (lane & 15) };
    const int bRow[4] = { wn * 64 + 0 * 16 + ((lane >> 4) << 3) + (lane & 7),
                          wn * 64 + 1 * 16 + ((lane >> 4) << 3) + (lane & 7),
                          wn * 64 + 2 * 16 + ((lane >> 4) << 3) + (lane & 7),
                          wn * 64 + 3 * 16 + ((lane >> 4) << 3) + (lane & 7) };
    const uint32_t aKsel = ((lane >> 4) << 4);          // 0 or 16
    const uint32_t bKsel = (((lane >> 3) & 1) << 4);    // 0 or 16

    // per-thread cp.async coords
    const int lr = tid >> 3;          // 0..15
    const int lg = tid & 7;
    const uint32_t swOff = (uint32_t)(((lg * 16) ^ ((lr & 7) << 4)));

    auto loadAB = [&](int c) {
        const uint32_t aB = sb + (uint32_t)(c % STAGES) * (A_SZ + B_SZ);
        const uint32_t bB = aB + A_SZ;
        const int k0 = c * BK;
        const __half* aSrc = g_Xh + (size_t)(bm + lr) * K_DIM + k0 + lg * 8;
        const __half* bSrc = g_Wt + (size_t)(bn + lr) * K_DIM + k0 + lg * 8;
#pragma unroll
        for (int i = 0; i < 8; ++i)
            cp16(aB + (uint32_t)((lr + i * 16) * 128) + swOff,
                 aSrc + (size_t)(i * 16) * K_DIM);
#pragma unroll
        for (int i = 0; i < 8; ++i)
            cp16(bB + (uint32_t)((lr + i * 16) * 128) + swOff,
                 bSrc + (size_t)(i * 16) * K_DIM);
        asm volatile("cp.async.commit_group;" ::: "memory");
    };

    // fragment loader for one kk step
    auto loadFrags = [&](uint32_t aB, uint32_t bB, int kk,
                         uint32_t a[4][4], uint32_t b[4][4]) {
        const uint32_t kb = (uint32_t)kk * 32;
#pragma unroll
        for (int j = 0; j < 4; ++j)
            ldsm4(b[j], bB + bRow[j] * 128 +
                        ((kb + bKsel) ^ ((bRow[j] & 7) << 4)));
#pragma unroll
        for (int i = 0; i < 4; ++i)
            ldsm4(a[i], aB + aRow[i] * 128 +
                        ((kb + aKsel) ^ ((aRow[i] & 7) << 4)));
    };

    auto mmaStep = [&](uint32_t a[4][4], uint32_t b[4][4]) {
#pragma unroll
        for (int i = 0; i < 4; ++i)
#pragma unroll
            for (int j = 0; j < 4; ++j) {
                mma16816(acc[i][2 * j],     a[i], b[j][0], b[j][1]);
                mma16816(acc[i][2 * j + 1], a[i], b[j][2], b[j][3]);
            }
    };

    // ---- prologue: stages 0 and 1 in flight ----
    loadAB(0);
    loadAB(1);

    uint32_t a0[4][4], b0[4][4], a1[4][4], b1[4][4];

    for (int c = 0; c < CHUNKS; ++c) {
        if (c == CHUNKS - 1) {
            asm volatile("cp.async.wait_group 0;" ::: "memory");
        } else {
            asm volatile("cp.async.wait_group 1;" ::: "memory");
        }
        __syncthreads();   // stage(c) visible; MMA(c-1) fully retired

        const uint32_t aB = sb + (uint32_t)(c % STAGES) * (A_SZ + B_SZ);
        const uint32_t bB = aB + A_SZ;

        // kk=0 fragments (exposed LDSM, once per chunk)
        loadFrags(aB, bB, 0, a0, b0);
        // kk=1 fragments issue, then kk=0 MMAs run under them
        loadFrags(aB, bB, 1, a1, b1);
        mmaStep(a0, b0);
        // cp.async for c+2 overlaps the remaining MMAs
        if (c + 2 < CHUNKS) loadAB(c + 2);
        loadFrags(aB, bB, 2, a0, b0);
        mmaStep(a1, b1);
        loadFrags(aB, bB, 3, a1, b1);
        mmaStep(a0, b0);
        mmaStep(a1, b1);
    }

    // ---- epilogue: out = rnd16(acc)  (scales already folded into W) ----
#pragma unroll
    for (int i = 0; i < 4; ++i) {
        const int m0 = bm + wm * 64 + i * 16 + (lane >> 2);
        float* y0 = Y + (size_t)m0 * N_DIM;
        float* y1 = y0 + (size_t)8 * N_DIM;
#pragma unroll
        for (int jj = 0; jj < 8; ++jj) {
            const int n0 = bn + wn * 64 + jj * 8 + 2 * (lane & 3);
            float2 v0, v1;
            v0.x = rnd16(acc[i][jj][0]);
            v0.y = rnd16(acc[i][jj][1]);
            v1.x = rnd16(acc[i][jj][2]);
            v1.y = rnd16(acc[i][jj][3]);
            *reinterpret_cast<float2*>(y0 + n0) = v0;
            *reinterpret_cast<float2*>(y1 + n0) = v1;
        }
    }
}

// ---------------------------------------------------------------------------
extern "C" void kernel_launch(void* const* d_in, const int* in_sizes, int n_in,
                              void* d_out, int out_size) {
    const float* x       = (const float*)d_in[0];
    const int*   qweight = (const int*)d_in[1];
    const int*   qzeros  = (const int*)d_in[2];
    const float* scales  = (const float*)d_in[3];
    float*       out     = (float*)d_out;

    cudaFuncSetAttribute(gemm_mma,
                         cudaFuncAttributeMaxDynamicSharedMemorySize, SMEM_BYTES);

    prep<<<XBLK + WBLK, 256>>>(x, qweight, qzeros, scales);

    dim3 grid(N_DIM / BN, M_DIM / BM);   // 86 x 32
    gemm_mma<<<grid, NTHREADS, SMEM_BYTES>>>(out);
}

// round 14
// speedup vs baseline: 1.0450x; 1.0450x over previous
#include <cuda_runtime.h>
#include <cuda_fp16.h>
#include <cstdint>
#include <cstddef>

// ---------------------------------------------------------------------------
// GPTQ 4-bit: merged prep pass (X f32->f16 + W dequant) + persistent-CTA
// streaming fp16 HMMA GEMM, sm_103 base arch.
//
// R14 vs R12 (best=788us): persistent CTAs (grid = 2 per SM). Each CTA walks
// tiles with stride gridDim.x; at the last two chunks of a tile the cp.async
// prefetch targets chunks 0/1 of the CTA's NEXT tile, so the epilogue and
// tile-switch run entirely under in-flight loads - no cold prologue per tile,
// no wave tail. Stage ring (mod 3) and the 1-barrier-per-chunk discipline
// continue unbroken across tile boundaries. MMA body identical to R12.
//
//   x      : float32 [4096, 4096]
//   qweight: int32   [512, 11008]  nibble j (shift 4*j) -> k = kp*8 + j
//   qzeros : int32   [1, 1376]     nibble (n%8) -> zero for col n; +1 (GPTQ)
//   scales : float32 [1, 11008]
//   out    : float32 [4096, 11008]
//
// K-permutation: g_Xh and g_Wt store each 8-group of K in pair order
// (t, t+4), matching ((q >> 4t) & 0x000F000F) | 0x64006400. Contraction is
// permutation-invariant. Dequant exact: w = ((1024+q) - (1025+z)) * s.
// ---------------------------------------------------------------------------

static constexpr int M_DIM = 4096;
static constexpr int K_DIM = 4096;
static constexpr int N_DIM = 11008;

static constexpr int BM = 128;
static constexpr int BN = 128;
static constexpr int BK = 64;                    // halves (128 B)
static constexpr int CHUNKS = K_DIM / BK;        // 64
static constexpr int STAGES = 3;
static constexpr int NTHREADS = 128;             // 4 warps
static constexpr int PGRID = 304;                // 2 CTAs x 152 SMs

static constexpr uint32_t A_SZ = BM * 128;       // 16 KB
static constexpr uint32_t B_SZ = BN * 128;       // 16 KB
static constexpr uint32_t SMEM_BYTES = STAGES * (A_SZ + B_SZ);  // 96 KB

__device__ __half g_Xh[(size_t)M_DIM * K_DIM];   // 32 MB
__device__ __half g_Wt[(size_t)N_DIM * K_DIM];   // 90 MB, W^T [N][K]

// ---------------- helpers ----------------
__device__ __forceinline__ uint32_t h2u(__half2 h) { return *reinterpret_cast<uint32_t*>(&h); }
__device__ __forceinline__ __half2  u2h(uint32_t u) { return *reinterpret_cast<__half2*>(&u); }
__device__ __forceinline__ float    rnd16(float x) { return __half2float(__float2half_rn(x)); }

__device__ __forceinline__ void cp16(uint32_t dst, const void* src) {
    asm volatile("cp.async.cg.shared.global [%0], [%1], 16;" :: "r"(dst), "l"(src));
}
__device__ __forceinline__ void ldsm4(uint32_t* r, uint32_t addr) {
    asm volatile("ldmatrix.sync.aligned.m8n8.x4.shared.b16 {%0,%1,%2,%3}, [%4];"
                 : "=r"(r[0]), "=r"(r[1]), "=r"(r[2]), "=r"(r[3]) : "r"(addr));
}
__device__ __forceinline__ void mma16816(float* c, const uint32_t* a,
                                         uint32_t b0, uint32_t b1) {
    asm volatile("mma.sync.aligned.m16n8k16.row.col.f32.f16.f16.f32 "
                 "{%0,%1,%2,%3}, {%4,%5,%6,%7}, {%8,%9}, {%0,%1,%2,%3};"
                 : "+f"(c[0]), "+f"(c[1]), "+f"(c[2]), "+f"(c[3])
                 : "r"(a[0]), "r"(a[1]), "r"(a[2]), "r"(a[3]), "r"(b0), "r"(b1));
}

// ---------------------------------------------------------------------------
// Merged prep: blocks [0, XBLK) convert X; blocks [XBLK, XBLK+WBLK) dequant W.
// ---------------------------------------------------------------------------
static constexpr int XGROUPS = M_DIM * (K_DIM / 8);            // 2M
static constexpr int XBLK    = XGROUPS / 256;                   // 8192
static constexpr long long WGROUPS = (long long)N_DIM * (K_DIM / 16);
static constexpr int WBLK    = (int)((WGROUPS + 255) / 256);    // 11008

__global__ void __launch_bounds__(256)
prep(const float* __restrict__ X,
     const int*   __restrict__ qweight,
     const int*   __restrict__ qzeros,
     const float* __restrict__ scales) {
    if (blockIdx.x < XBLK) {
        const size_t e = (size_t)blockIdx.x * 256 + threadIdx.x;
        const float4* s = reinterpret_cast<const float4*>(X) + e * 2;
        const float4 lo = s[0];
        const float4 hi = s[1];
        uint4 o;
        o.x = h2u(__floats2half2_rn(lo.x, hi.x));
        o.y = h2u(__floats2half2_rn(lo.y, hi.y));
        o.z = h2u(__floats2half2_rn(lo.z, hi.z));
        o.w = h2u(__floats2half2_rn(lo.w, hi.w));
        reinterpret_cast<uint4*>(g_Xh)[e] = o;
    } else {
        const size_t idx = (size_t)(blockIdx.x - XBLK) * 256 + threadIdx.x;
        if (idx >= (size_t)WGROUPS) return;
        const int n   = (int)(idx % N_DIM);
        const int kp2 = (int)(idx / N_DIM);      // 0..255
        const int kp  = kp2 * 2;

        const int zraw = (qzeros[n >> 3] >> ((n & 7) * 4)) & 0xF;
        const __half2 z2 = __half2half2(__float2half_rn((float)(1025 + zraw)));
        const __half2 s2 = __half2half2(__float2half_rn(scales[n]));

        __half* dst = g_Wt + (size_t)n * K_DIM + kp * 8;
#pragma unroll
        for (int w2 = 0; w2 < 2; ++w2) {
            const uint32_t w = (uint32_t)qweight[(size_t)(kp + w2) * N_DIM + n];
            uint4 o;
            uint32_t* u = reinterpret_cast<uint32_t*>(&o);
#pragma unroll
            for (int t = 0; t < 4; ++t) {
                const uint32_t hb = ((w >> (4 * t)) & 0x000F000Fu) | 0x64006400u;
                u[t] = h2u(__hmul2(__hsub2(u2h(hb), z2), s2));
            }
            *reinterpret_cast<uint4*>(dst + w2 * 8) = o;
        }
    }
}

// ---------------------------------------------------------------------------
// Persistent streaming GEMM: CTA tile 128x128x64, 4 warps (2m x 2n of 64x64),
// cp.async 3-stage ring continuing across tiles, 1 barrier/chunk, 2 CTAs/SM.
// ---------------------------------------------------------------------------
__global__ void __launch_bounds__(NTHREADS, 2)
gemm_mma(float* __restrict__ Y) {
    extern __shared__ char smem[];
    const uint32_t sb = (uint32_t)__cvta_generic_to_shared(smem);

    const int tid  = threadIdx.x;
    const int warp = tid >> 5;
    const int lane = tid & 31;
    const int wm   = warp >> 1;      // 0..1  (64-row slice)
    const int wn   = warp & 1;       // 0..1  (64-col slice)

    // per-thread cp.async coords
    const int lr = tid >> 3;          // 0..15
    const int lg = tid & 7;
    const uint32_t swOff = (uint32_t)(((lg * 16) ^ ((lr & 7) << 4)));

    auto loadAB = [&](int bm, int bn, int c, int stg) {
        const uint32_t aB = sb + (uint32_t)stg * (A_SZ + B_SZ);
        const uint32_t bB = aB + A_SZ;
        const int k0 = c * BK;
        const __half* aSrc = g_Xh + (size_t)(bm + lr) * K_DIM + k0 + lg * 8;
        const __half* bSrc = g_Wt + (size_t)(bn + lr) * K_DIM + k0 + lg * 8;
#pragma unroll
        for (int i = 0; i < 8; ++i)
            cp16(aB + (uint32_t)((lr + i * 16) * 128) + swOff,
                 aSrc + (size_t)(i * 16) * K_DIM);
#pragma unroll
        for (int i = 0; i < 8; ++i)
            cp16(bB + (uint32_t)((lr + i * 16) * 128) + swOff,
                 bSrc + (size_t)(i * 16) * K_DIM);
        asm volatile("cp.async.commit_group;" ::: "memory");
    };

    const int NBN  = N_DIM / BN;                 // 86
    const int NT   = NBN * (M_DIM / BM);         // 2752
    const int step = gridDim.x;

    int t  = blockIdx.x;
    if (t >= NT) return;
    int bm = (t / NBN) * BM;
    int bn = (t % NBN) * BN;

    // prologue: first tile, stages 0 and 1
    loadAB(bm, bn, 0, 0);
    loadAB(bm, bn, 1, 1);
    int sRead = 0;

    while (t < NT) {
        const int  tn      = t + step;
        const bool hasNext = tn < NT;
        const int  nbm     = hasNext ? (tn / NBN) * BM : 0;
        const int  nbn     = hasNext ? (tn % NBN) * BN : 0;

        float acc[4][8][4];
#pragma unroll
        for (int i = 0; i < 4; ++i)
#pragma unroll
            for (int j = 0; j < 8; ++j)
#pragma unroll
                for (int v = 0; v < 4; ++v) acc[i][j][v] = 0.0f;

        for (int c = 0; c < CHUNKS; ++c) {
            if (!hasNext && c == CHUNKS - 1) {
                asm volatile("cp.async.wait_group 0;" ::: "memory");
            } else {
                asm volatile("cp.async.wait_group 1;" ::: "memory");
            }
            __syncthreads();   // stage(sRead) visible; prev MMA fully retired

            const uint32_t aB = sb + (uint32_t)sRead * (A_SZ + B_SZ);
            const uint32_t bB = aB + A_SZ;
#pragma unroll
            for (int kk = 0; kk < 4; ++kk) {
                const uint32_t kb = kk * 32;
                uint32_t a[4][4], b[4][4];
#pragma unroll
                for (int j = 0; j < 4; ++j) {
                    const int row = wn * 64 + j * 16 + ((lane >> 4) << 3) + (lane & 7);
                    const uint32_t addr = bB + row * 128 +
                        ((kb + (((lane >> 3) & 1) << 4)) ^ ((row & 7) << 4));
                    ldsm4(b[j], addr);
                }
#pragma unroll
                for (int i = 0; i < 4; ++i) {
                    const int row = wm * 64 + i * 16 + (lane & 15);
                    const uint32_t addr = aB + row * 128 +
                        ((kb + ((lane >> 4) << 4)) ^ ((row & 7) << 4));
                    ldsm4(a[i], addr);
                }
#pragma unroll
                for (int i = 0; i < 4; ++i)
#pragma unroll
                    for (int j = 0; j < 4; ++j) {
                        mma16816(acc[i][2 * j],     a[i], b[j][0], b[j][1]);
                        mma16816(acc[i][2 * j + 1], a[i], b[j][2], b[j][3]);
                    }
            }

            // prefetch: current tile c+2, or next tile's chunks 0/1
            const int wstg = (sRead >= 1) ? sRead - 1 : 2;   // (sRead+2)%3
            if (c + 2 < CHUNKS) {
                loadAB(bm, bn, c + 2, wstg);
            } else if (hasNext) {
                loadAB(nbm, nbn, c + 2 - CHUNKS, wstg);
            }
            sRead = (sRead == 2) ? 0 : sRead + 1;
        }

        // ---- epilogue (runs under next tile's in-flight cp.async) ----
#pragma unroll
        for (int i = 0; i < 4; ++i) {
            const int m0 = bm + wm * 64 + i * 16 + (lane >> 2);
            float* y0 = Y + (size_t)m0 * N_DIM;
            float* y1 = y0 + (size_t)8 * N_DIM;
#pragma unroll
            for (int jj = 0; jj < 8; ++jj) {
                const int n0 = bn + wn * 64 + jj * 8 + 2 * (lane & 3);
                float2 v0, v1;
                v0.x = rnd16(acc[i][jj][0]);
                v0.y = rnd16(acc[i][jj][1]);
                v1.x = rnd16(acc[i][jj][2]);
                v1.y = rnd16(acc[i][jj][3]);
                *reinterpret_cast<float2*>(y0 + n0) = v0;
                *reinterpret_cast<float2*>(y1 + n0) = v1;
            }
        }

        t  = tn;
        bm = nbm;
        bn = nbn;
    }
}

// ---------------------------------------------------------------------------
extern "C" void kernel_launch(void* const* d_in, const int* in_sizes, int n_in,
                              void* d_out, int out_size) {
    const float* x       = (const float*)d_in[0];
    const int*   qweight = (const int*)d_in[1];
    const int*   qzeros  = (const int*)d_in[2];
    const float* scales  = (const float*)d_in[3];
    float*       out     = (float*)d_out;

    cudaFuncSetAttribute(gemm_mma,
                         cudaFuncAttributeMaxDynamicSharedMemorySize, SMEM_BYTES);

    prep<<<XBLK + WBLK, 256>>>(x, qweight, qzeros, scales);

    gemm_mma<<<PGRID, NTHREADS, SMEM_BYTES>>>(out);
}